// round 1
// baseline (speedup 1.0000x reference)
#include <cuda_runtime.h>
#include <math.h>

#define BATCH 8
#define CH    2048
#define LPIX  784
#define DD    8192
#define NCLS  200

// Scratch (no allocations allowed): Gram matrices + bin accumulator
__device__ float d_G[(size_t)BATCH * CH * CH];   // 134 MB
__device__ float d_y[BATCH * DD];

// ---------------------------------------------------------------- zero y ----
__global__ void zero_y_kernel() {
    int i = blockIdx.x * blockDim.x + threadIdx.x;
    if (i < BATCH * DD) d_y[i] = 0.f;
}

// ------------------------------------------------------ Gram: G = X X^T ----
#define BM 128
#define BK 8
#define NBLK  (CH / BM)                  // 16
#define NPAIR (NBLK * (NBLK + 1) / 2)    // 136 (upper-triangle block pairs)

__global__ __launch_bounds__(256) void gram_kernel(const float* __restrict__ x) {
    int b = blockIdx.y;
    int pair = blockIdx.x;
    // decode (bi, bj), bi <= bj
    int bi = 0, rem = pair;
    while (rem >= NBLK - bi) { rem -= NBLK - bi; bi++; }
    int bj = bi + rem;

    const float* X = x + (size_t)b * CH * LPIX;

    __shared__ __align__(16) float As[BK][BM];
    __shared__ __align__(16) float Bs[BK][BM];

    int tid = threadIdx.x;
    int tx = tid & 15;           // 0..15
    int ty = tid >> 4;           // 0..15
    int lrow = tid >> 1;         // 0..127
    int lseg = (tid & 1) * 4;    // 0 or 4

    float acc[8][8];
#pragma unroll
    for (int i = 0; i < 8; i++)
#pragma unroll
        for (int j = 0; j < 8; j++) acc[i][j] = 0.f;

    const float* Arow = X + (size_t)(bi * BM + lrow) * LPIX + lseg;
    const float* Brow = X + (size_t)(bj * BM + lrow) * LPIX + lseg;

    for (int l0 = 0; l0 < LPIX; l0 += BK) {
        float4 av = *(const float4*)(Arow + l0);
        float4 bv = *(const float4*)(Brow + l0);
        As[lseg + 0][lrow] = av.x;
        As[lseg + 1][lrow] = av.y;
        As[lseg + 2][lrow] = av.z;
        As[lseg + 3][lrow] = av.w;
        Bs[lseg + 0][lrow] = bv.x;
        Bs[lseg + 1][lrow] = bv.y;
        Bs[lseg + 2][lrow] = bv.z;
        Bs[lseg + 3][lrow] = bv.w;
        __syncthreads();

#pragma unroll
        for (int kk = 0; kk < BK; kk++) {
            float a[8], bb[8];
            *(float4*)&a[0]  = *(const float4*)&As[kk][ty * 8];
            *(float4*)&a[4]  = *(const float4*)&As[kk][ty * 8 + 4];
            *(float4*)&bb[0] = *(const float4*)&Bs[kk][tx * 8];
            *(float4*)&bb[4] = *(const float4*)&Bs[kk][tx * 8 + 4];
#pragma unroll
            for (int i = 0; i < 8; i++)
#pragma unroll
                for (int j = 0; j < 8; j++)
                    acc[i][j] += a[i] * bb[j];
        }
        __syncthreads();
    }

    float* Gb = d_G + (size_t)b * CH * CH;
    int r0 = bi * BM + ty * 8;
    int c0 = bj * BM + tx * 8;
#pragma unroll
    for (int i = 0; i < 8; i++) {
        *(float4*)&Gb[(size_t)(r0 + i) * CH + c0] =
            make_float4(acc[i][0], acc[i][1], acc[i][2], acc[i][3]);
        *(float4*)&Gb[(size_t)(r0 + i) * CH + c0 + 4] =
            make_float4(acc[i][4], acc[i][5], acc[i][6], acc[i][7]);
    }
    if (bi != bj) {
#pragma unroll
        for (int j = 0; j < 8; j++) {
            *(float4*)&Gb[(size_t)(c0 + j) * CH + r0] =
                make_float4(acc[0][j], acc[1][j], acc[2][j], acc[3][j]);
            *(float4*)&Gb[(size_t)(c0 + j) * CH + r0 + 4] =
                make_float4(acc[4][j], acc[5][j], acc[6][j], acc[7][j]);
        }
    }
}

// -------------------------------------------------- scatter into D bins ----
#define SROWS 32
__global__ __launch_bounds__(256) void scatter_kernel(const float* __restrict__ s1,
                                                      const float* __restrict__ s2,
                                                      const int* __restrict__ h1,
                                                      const int* __restrict__ h2) {
    __shared__ float bins[DD];   // 32 KB privatized accumulator
    int tid = threadIdx.x;
    int b = blockIdx.y;
    int strip = blockIdx.x;

    for (int i = tid; i < DD; i += 256) bins[i] = 0.f;

    // each thread owns 8 fixed c2 values -> cache s2/h2 in registers
    float s2r[8];
    int   h2r[8];
#pragma unroll
    for (int k = 0; k < 8; k++) {
        int c2 = tid + k * 256;
        s2r[k] = s2[c2];
        h2r[k] = h2[c2];
    }
    __syncthreads();

    for (int r = 0; r < SROWS; r++) {
        int c1 = strip * SROWS + r;
        float s1v = s1[c1];
        int h1v = h1[c1];
        const float* Grow = d_G + ((size_t)b * CH + c1) * CH;
#pragma unroll
        for (int k = 0; k < 8; k++) {
            int c2 = tid + k * 256;
            float v = Grow[c2] * (s1v * s2r[k]);
            int bin = h1v + h2r[k];
            if (bin >= DD) bin -= DD;
            atomicAdd(&bins[bin], v);
        }
    }
    __syncthreads();

    float* yb = d_y + b * DD;
    for (int i = tid; i < DD; i += 256) atomicAdd(&yb[i], bins[i]);
}

// ------------------------------ epilogue: signed sqrt, L2 norm, classifier ----
__global__ __launch_bounds__(1024) void epilogue_kernel(const float* __restrict__ Wc,
                                                        const float* __restrict__ bc,
                                                        float* __restrict__ out_logit,
                                                        float* __restrict__ out_feat) {
    int b = blockIdx.x;
    int tid = threadIdx.x;
    __shared__ float feat[DD];       // 32 KB
    __shared__ float red[32];
    __shared__ float part[4][256];

    const float* yb = d_y + b * DD;
    float ss = 0.f;
    for (int i = tid; i < DD; i += 1024) {
        float v = yb[i];
        float f = copysignf(sqrtf(fabsf(v)), v);
        feat[i] = f;
        ss += f * f;
    }
#pragma unroll
    for (int o = 16; o > 0; o >>= 1) ss += __shfl_xor_sync(0xffffffffu, ss, o);
    if ((tid & 31) == 0) red[tid >> 5] = ss;
    __syncthreads();
    if (tid < 32) {
        float v = red[tid];
#pragma unroll
        for (int o = 16; o > 0; o >>= 1) v += __shfl_xor_sync(0xffffffffu, v, o);
        if (tid == 0) red[0] = v;
    }
    __syncthreads();
    float inv = 1.f / fmaxf(sqrtf(red[0]), 1e-12f);

    for (int i = tid; i < DD; i += 1024) {
        float f = feat[i] * inv;
        feat[i] = f;
        if (out_feat) out_feat[(size_t)b * DD + i] = f;
    }
    __syncthreads();

    if (out_logit) {
        int g = tid >> 8;     // 0..3  (d-range partition)
        int n = tid & 255;    // class id (first 200 active)
        float acc = 0.f;
        if (n < NCLS) {
            int d0 = g * (DD / 4);
            const float* Wp = Wc + (size_t)d0 * NCLS + n;
#pragma unroll 8
            for (int d = 0; d < DD / 4; d++) {
                acc += feat[d0 + d] * Wp[(size_t)d * NCLS];
            }
        }
        part[g][n] = acc;
        __syncthreads();
        if (g == 0 && n < NCLS) {
            float l = bc[n] + part[0][n] + part[1][n] + part[2][n] + part[3][n];
            out_logit[(size_t)b * NCLS + n] = l;
        }
    }
}

// --------------------------------------------------------------------------
extern "C" void kernel_launch(void* const* d_in, const int* in_sizes, int n_in,
                              void* d_out, int out_size) {
    const float* x  = (const float*)d_in[0];
    const float* s1 = (const float*)d_in[1];
    const float* s2 = (const float*)d_in[2];
    const float* Wc = (const float*)d_in[3];
    const float* bc = (const float*)d_in[4];
    const int*   h1 = (const int*)d_in[5];
    const int*   h2 = (const int*)d_in[6];

    float* out = (float*)d_out;
    float* out_logit = nullptr;
    float* out_feat  = nullptr;
    if (out_size >= BATCH * NCLS + BATCH * DD) {
        out_logit = out;                      // logit first, then feat
        out_feat  = out + BATCH * NCLS;
    } else if (out_size == BATCH * DD) {
        out_feat = out;
    } else {
        out_logit = out;
    }

    zero_y_kernel<<<(BATCH * DD + 255) / 256, 256>>>();

    dim3 ggrid(NPAIR, BATCH);
    gram_kernel<<<ggrid, 256>>>(x);

    dim3 sgrid(CH / SROWS, BATCH);
    scatter_kernel<<<sgrid, 256>>>(s1, s2, h1, h2);

    epilogue_kernel<<<BATCH, 1024>>>(Wc, bc, out_logit, out_feat);
}

// round 3
// speedup vs baseline: 3.1259x; 3.1259x over previous
#include <cuda_runtime.h>
#include <cuda_fp16.h>
#include <cstdint>
#include <math.h>

#define BATCH 8
#define CH    2048
#define LPIX  784
#define KP    800            // LPIX padded to multiple of 32
#define DD    8192
#define NCLS  200
#define BM    128
#define NBLK  (CH / BM)                  // 16
#define NPAIR (NBLK * (NBLK + 1) / 2)    // 136
#define NCHUNK (KP / 32)                 // 25

// ---- scratch (__device__ globals; no allocations allowed) ----
__device__ __align__(16) __half d_xh[(size_t)BATCH * CH * KP];
__device__ __align__(16) __half d_xl[(size_t)BATCH * CH * KP];
__device__ float d_y[BATCH * DD];
__device__ float d_featn[BATCH * DD];

// ============================ helpers ============================
__device__ __forceinline__ uint32_t s2u(const void* p) {
    uint32_t a;
    asm("{ .reg .u64 t; cvta.to.shared.u64 t, %1; cvt.u32.u64 %0, t; }" : "=r"(a) : "l"(p));
    return a;
}
__device__ __forceinline__ void cp_async16(uint32_t saddr, const void* gptr) {
    asm volatile("cp.async.cg.shared.global [%0], [%1], 16;" :: "r"(saddr), "l"(gptr));
}
__device__ __forceinline__ void cp_commit() { asm volatile("cp.async.commit_group;"); }
__device__ __forceinline__ void ldsm4(uint32_t* r, uint32_t addr) {
    asm volatile("ldmatrix.sync.aligned.m8n8.x4.shared.b16 {%0,%1,%2,%3}, [%4];"
                 : "=r"(r[0]), "=r"(r[1]), "=r"(r[2]), "=r"(r[3]) : "r"(addr));
}
__device__ __forceinline__ void mma16816(float* c, const uint32_t* a, uint32_t b0, uint32_t b1) {
    asm volatile("mma.sync.aligned.m16n8k16.row.col.f32.f16.f16.f32 "
                 "{%0,%1,%2,%3}, {%4,%5,%6,%7}, {%8,%9}, {%0,%1,%2,%3};"
                 : "+f"(c[0]), "+f"(c[1]), "+f"(c[2]), "+f"(c[3])
                 : "r"(a[0]), "r"(a[1]), "r"(a[2]), "r"(a[3]), "r"(b0), "r"(b1));
}
__device__ __forceinline__ void red_shared_f32(uint32_t addr, float v) {
    asm volatile("red.shared.add.f32 [%0], %1;" :: "r"(addr), "f"(v) : "memory");
}

// smem stage layout: 4 arrays (Ah, Al, Bh, Bl), each 128 rows x 40 halves (80 B/row)
#define ARR_B   10240
#define STAGE_B 40960
#define DYN_B   (2 * STAGE_B)    // 81920

// ============================ prep: fp32 -> fp16 hi/lo (K-padded) ============================
__global__ __launch_bounds__(256) void prep_kernel(const float* __restrict__ x) {
    size_t idx = (size_t)blockIdx.x * 256 + threadIdx.x;
    if (idx >= (size_t)BATCH * CH * KP) return;
    int l = (int)(idx % KP);
    size_t rc = idx / KP;
    float v = 0.f;
    if (l < LPIX) v = x[rc * LPIX + l];
    __half h = __float2half(v);
    float r = v - __half2float(h);
    d_xh[idx] = h;
    d_xl[idx] = __float2half(r);
}

__global__ void zero_y_kernel() {
    int i = blockIdx.x * blockDim.x + threadIdx.x;
    if (i < BATCH * DD) d_y[i] = 0.f;
}

// ============================ fused Gram-MMA + count-sketch scatter ============================
__global__ __launch_bounds__(256, 2)
void gram_scatter_kernel(const float* __restrict__ s1, const float* __restrict__ s2,
                         const int* __restrict__ h1, const int* __restrict__ h2) {
    extern __shared__ __align__(16) char sraw[];
    int tid = threadIdx.x;
    int wid = tid >> 5, lane = tid & 31;
    int wm = wid >> 2, wn = wid & 3;             // 2 x 4 warp grid
    int b = blockIdx.y;
    int pair = blockIdx.x;
    int bi = 0, rem = pair;
    while (rem >= NBLK - bi) { rem -= NBLK - bi; bi++; }
    int bj = bi + rem;

    uint32_t dyn_u = (s2u(sraw) + 127) & ~127u;
    char* dynp = sraw + (dyn_u - s2u(sraw));

    const __half* Ah = d_xh + ((size_t)b * CH + (size_t)bi * BM) * KP;
    const __half* Al = d_xl + ((size_t)b * CH + (size_t)bi * BM) * KP;
    const __half* Bh = d_xh + ((size_t)b * CH + (size_t)bj * BM) * KP;
    const __half* Bl = d_xl + ((size_t)b * CH + (size_t)bj * BM) * KP;

    float acc[4][4][4];
#pragma unroll
    for (int i = 0; i < 4; i++)
#pragma unroll
        for (int j = 0; j < 4; j++)
#pragma unroll
            for (int k = 0; k < 4; k++) acc[i][j][k] = 0.f;

    // ---- load issuer ----
    auto issue = [&](int chunk, int stage) {
        uint32_t sb = dyn_u + stage * STAGE_B;
#pragma unroll
        for (int i = 0; i < 2; i++) {
            int idx = tid + i * 256;            // 0..511
            int row = idx >> 2, ck = idx & 3;
            size_t go = (size_t)row * KP + (size_t)chunk * 32 + (size_t)ck * 8;
            uint32_t so = sb + row * 80 + ck * 16;
            cp_async16(so + 0 * ARR_B, Ah + go);
            cp_async16(so + 1 * ARR_B, Al + go);
            cp_async16(so + 2 * ARR_B, Bh + go);
            cp_async16(so + 3 * ARR_B, Bl + go);
        }
        cp_commit();
    };

    issue(0, 0);

    int lrow = lane & 15, lk = lane >> 4;

    for (int c = 0; c < NCHUNK; c++) {
        int cur = c & 1;
        if (c + 1 < NCHUNK) {
            issue(c + 1, (c + 1) & 1);
            asm volatile("cp.async.wait_group 1;" ::: "memory");
        } else {
            asm volatile("cp.async.wait_group 0;" ::: "memory");
        }
        __syncthreads();

        uint32_t base = dyn_u + cur * STAGE_B;
        uint32_t aHb = base + 0 * ARR_B, aLb = base + 1 * ARR_B;
        uint32_t bHb = base + 2 * ARR_B, bLb = base + 3 * ARR_B;

#pragma unroll
        for (int ks = 0; ks < 2; ks++) {
            uint32_t coff = (uint32_t)(ks * 16 + lk * 8) * 2;
            uint32_t bh[2][4], bl[2][4];
#pragma unroll
            for (int g = 0; g < 2; g++) {
                uint32_t r = (uint32_t)(wn * 32 + g * 16 + lrow);
                ldsm4(bh[g], bHb + r * 80 + coff);
                ldsm4(bl[g], bLb + r * 80 + coff);
            }
#pragma unroll
            for (int mf = 0; mf < 4; mf++) {
                uint32_t r = (uint32_t)(wm * 64 + mf * 16 + lrow);
                uint32_t ah[4], al[4];
                ldsm4(ah, aHb + r * 80 + coff);
                ldsm4(al, aLb + r * 80 + coff);
#pragma unroll
                for (int nf = 0; nf < 4; nf++) {
                    int g = nf >> 1, s = nf & 1;
                    mma16816(acc[mf][nf], ah, bh[g][s], bh[g][s + 2]);
                    mma16816(acc[mf][nf], ah, bl[g][s], bl[g][s + 2]);
                    mma16816(acc[mf][nf], al, bh[g][s], bh[g][s + 2]);
                }
            }
        }
        __syncthreads();
    }

    // ================= epilogue: scatter acc into smem bins =================
    float* bins = (float*)dynp;
    int*   h1r = (int*)  (dynp + 32768);
    float* s1r = (float*)(dynp + 33280);
    int*   h2c = (int*)  (dynp + 33792);
    float* s2c = (float*)(dynp + 34304);
    int*   h1m = (int*)  (dynp + 34816);
    float* s1m = (float*)(dynp + 35328);
    int*   h2m = (int*)  (dynp + 35840);
    float* s2m = (float*)(dynp + 36352);

    for (int i = tid; i < DD; i += 256) bins[i] = 0.f;
    if (tid < BM) {
        int ci = bi * BM + tid, cj = bj * BM + tid;
        h1r[tid] = h1[ci]; s1r[tid] = s1[ci];
        h2c[tid] = h2[cj]; s2c[tid] = s2[cj];
        h1m[tid] = h1[cj]; s1m[tid] = s1[cj];
        h2m[tid] = h2[ci]; s2m[tid] = s2[ci];
    }
    __syncthreads();

    bool off = (bi != bj);
    int q = lane & 3, rbase = lane >> 2;

    // column lookups (8 values per thread)
    int h2c8[8], h1m8[8];
    float s2c8[8], s1m8[8];
#pragma unroll
    for (int nf = 0; nf < 4; nf++)
#pragma unroll
        for (int e = 0; e < 2; e++) {
            int n = wn * 32 + nf * 8 + 2 * q + e;
            int id = nf * 2 + e;
            h2c8[id] = h2c[n]; s2c8[id] = s2c[n];
            h1m8[id] = h1m[n]; s1m8[id] = s1m[n];
        }

#pragma unroll
    for (int mf = 0; mf < 4; mf++) {
#pragma unroll
        for (int half = 0; half < 2; half++) {
            int m = wm * 64 + mf * 16 + rbase + half * 8;
            int h1rv = h1r[m];
            float s1rv = s1r[m];
            int h2mv = h2m[m];
            float s2mv = s2m[m];
#pragma unroll
            for (int nf = 0; nf < 4; nf++)
#pragma unroll
                for (int e = 0; e < 2; e++) {
                    float v = acc[mf][nf][half * 2 + e];
                    int id = nf * 2 + e;
                    int b1 = h1rv + h2c8[id]; if (b1 >= DD) b1 -= DD;
                    red_shared_f32(dyn_u + (uint32_t)b1 * 4, v * s1rv * s2c8[id]);
                    if (off) {
                        int b2 = h1m8[id] + h2mv; if (b2 >= DD) b2 -= DD;
                        red_shared_f32(dyn_u + (uint32_t)b2 * 4, v * s1m8[id] * s2mv);
                    }
                }
        }
    }
    __syncthreads();

    float* yb = d_y + b * DD;
    for (int i = tid; i < DD; i += 256) {
        float v = bins[i];
        if (v != 0.f) atomicAdd(&yb[i], v);
    }
}

// ============================ normalize: signed sqrt + L2 ============================
__global__ __launch_bounds__(1024) void normalize_kernel(float* __restrict__ out_feat) {
    int b = blockIdx.x;
    int tid = threadIdx.x;
    __shared__ float feat[DD];
    __shared__ float red[32];

    const float* yb = d_y + b * DD;
    float ss = 0.f;
    for (int i = tid; i < DD; i += 1024) {
        float v = yb[i];
        float f = copysignf(sqrtf(fabsf(v)), v);
        feat[i] = f;
        ss += f * f;
    }
#pragma unroll
    for (int o = 16; o > 0; o >>= 1) ss += __shfl_xor_sync(0xffffffffu, ss, o);
    if ((tid & 31) == 0) red[tid >> 5] = ss;
    __syncthreads();
    if (tid < 32) {
        float v = red[tid];
#pragma unroll
        for (int o = 16; o > 0; o >>= 1) v += __shfl_xor_sync(0xffffffffu, v, o);
        if (tid == 0) red[0] = v;
    }
    __syncthreads();
    float inv = 1.f / fmaxf(sqrtf(red[0]), 1e-12f);

    for (int i = tid; i < DD; i += 1024) {
        float f = feat[i] * inv;
        d_featn[(size_t)b * DD + i] = f;
        if (out_feat) out_feat[(size_t)b * DD + i] = f;
    }
}

// ============================ classifier ============================
__global__ void init_logit_kernel(const float* __restrict__ bc, float* __restrict__ out_logit) {
    int i = blockIdx.x * blockDim.x + threadIdx.x;
    if (i < BATCH * NCLS) out_logit[i] = bc[i % NCLS];
}

#define DCH 32
__global__ __launch_bounds__(256) void classifier_kernel(const float* __restrict__ Wc,
                                                         float* __restrict__ out_logit) {
    __shared__ float ws[DCH * NCLS];
    __shared__ float fs[BATCH][DCH];
    int tid = threadIdx.x;
    int d0 = blockIdx.x * DCH;

    for (int i = tid; i < DCH * NCLS; i += 256) ws[i] = Wc[(size_t)d0 * NCLS + i];
    for (int i = tid; i < BATCH * DCH; i += 256) {
        int bb = i / DCH, dd = i % DCH;
        fs[bb][dd] = d_featn[(size_t)bb * DD + d0 + dd];
    }
    __syncthreads();

    int n = tid;
    if (n < NCLS) {
        float acc[BATCH];
#pragma unroll
        for (int bb = 0; bb < BATCH; bb++) acc[bb] = 0.f;
#pragma unroll 8
        for (int d = 0; d < DCH; d++) {
            float w = ws[d * NCLS + n];
#pragma unroll
            for (int bb = 0; bb < BATCH; bb++) acc[bb] += w * fs[bb][d];
        }
#pragma unroll
        for (int bb = 0; bb < BATCH; bb++)
            atomicAdd(&out_logit[bb * NCLS + n], acc[bb]);
    }
}

// ============================ launch ============================
extern "C" void kernel_launch(void* const* d_in, const int* in_sizes, int n_in,
                              void* d_out, int out_size) {
    const float* x  = (const float*)d_in[0];
    const float* s1 = (const float*)d_in[1];
    const float* s2 = (const float*)d_in[2];
    const float* Wc = (const float*)d_in[3];
    const float* bc = (const float*)d_in[4];
    const int*   h1 = (const int*)d_in[5];
    const int*   h2 = (const int*)d_in[6];

    float* out = (float*)d_out;
    float* out_logit = nullptr;
    float* out_feat  = nullptr;
    if (out_size >= BATCH * NCLS + BATCH * DD) {
        out_logit = out;
        out_feat  = out + BATCH * NCLS;
    } else if (out_size == BATCH * DD) {
        out_feat = out;
    } else {
        out_logit = out;
    }

    static bool attr_set = false;
    if (!attr_set) {
        cudaFuncSetAttribute(gram_scatter_kernel, cudaFuncAttributeMaxDynamicSharedMemorySize, DYN_B + 128);
        attr_set = true;
    }

    size_t prep_elems = (size_t)BATCH * CH * KP;
    prep_kernel<<<(unsigned)((prep_elems + 255) / 256), 256>>>(x);
    zero_y_kernel<<<(BATCH * DD + 255) / 256, 256>>>();

    dim3 ggrid(NPAIR, BATCH);
    gram_scatter_kernel<<<ggrid, 256, DYN_B + 128>>>(s1, s2, h1, h2);

    normalize_kernel<<<BATCH, 1024>>>(out_feat);

    if (out_logit) {
        init_logit_kernel<<<(BATCH * NCLS + 255) / 256, 256>>>(bc, out_logit);
        classifier_kernel<<<DD / DCH, 256>>>(Wc, out_logit);
    }
}